// round 3
// baseline (speedup 1.0000x reference)
#include <cuda_runtime.h>
#include <cuda_bf16.h>

// Problem constants
#define BB 4
#define CC_FEAT 96
#define HH 192
#define WW 192
#define HW (HH*WW)
#define MD 3
#define ND 49

// ---------------- scratch (device globals; no allocation allowed) ----------------
__device__ float g_flow [BB*2*HW];          // upsampled flow (B,2,192,192)
__device__ float g_feat2[BB*CC_FEAT*HW];    // warped features2
__device__ float g_corr [BB*ND*HW];         // correlation output (leaky)
__device__ float g_x1   [BB*128*HW];
__device__ float g_x2   [BB*64 *HW];
__device__ float g_x3   [BB*32 *HW];

// ---------------- f32x2 helpers (FFMA2: 2x fp32 throughput, PTX-only) ----------------
__device__ __forceinline__ unsigned long long pk2(float lo, float hi) {
    unsigned long long r;
    asm("mov.b64 %0, {%1, %2};" : "=l"(r) : "f"(lo), "f"(hi));
    return r;
}
__device__ __forceinline__ void upk2(unsigned long long v, float& lo, float& hi) {
    asm("mov.b64 {%0, %1}, %2;" : "=f"(lo), "=f"(hi) : "l"(v));
}
__device__ __forceinline__ void fma2(unsigned long long& d, unsigned long long a, unsigned long long b) {
    asm("fma.rn.f32x2 %0, %1, %2, %0;" : "+l"(d) : "l"(a), "l"(b));
}

// ---------------- 1) upflow: ConvTranspose2d(2,2,k=4,s=2,p=1, groups=2) ----------------
__global__ void __launch_bounds__(256) upflow_k(const float* __restrict__ fl,
                                                const float* __restrict__ w)
{
    int idx = blockIdx.x * 256 + threadIdx.x;
    if (idx >= BB*2*HW) return;
    int x = idx % WW;
    int y = (idx / WW) % HH;
    int g = (idx / HW) % 2;
    int b = idx / (2*HW);
    float acc = 0.f;
#pragma unroll
    for (int ky = 0; ky < 4; ky++) {
        int t = y + ky - 2;
        if (t & 1) continue;
        int iy = t >> 1;
        if (iy < 0 || iy >= 96) continue;
#pragma unroll
        for (int kx = 0; kx < 4; kx++) {
            int s = x + kx - 2;
            if (s & 1) continue;
            int ix = s >> 1;
            if (ix < 0 || ix >= 96) continue;
            // flipped kernel (w[:,:,::-1,::-1])
            acc += w[g*16 + (3-ky)*4 + (3-kx)] * fl[((b*2 + g)*96 + iy)*96 + ix];
        }
    }
    g_flow[idx] = acc;
}

// ---------------- 2) backwarp: bilinear warp of features2 by 2.5*flow ----------------
__global__ void __launch_bounds__(256) backwarp_k(const float* __restrict__ feat)
{
    int idx = blockIdx.x * 256 + threadIdx.x;
    if (idx >= BB*HW) return;
    int x = idx % WW;
    int y = (idx / WW) % HH;
    int b = idx / HW;

    float fx = 2.5f * g_flow[(b*2 + 0)*HW + y*WW + x];
    float fy = 2.5f * g_flow[(b*2 + 1)*HW + y*WW + x];
    float gx = (float)x + fx;
    float gy = (float)y + fy;
    float x0f = floorf(gx), y0f = floorf(gy);
    float wx = gx - x0f, wy = gy - y0f;
    int x0 = (int)x0f, y0 = (int)y0f;
    int x1 = x0 + 1,  y1 = y0 + 1;

    float v00 = (x0 >= 0 && x0 < WW && y0 >= 0 && y0 < HH) ? 1.f : 0.f;
    float v01 = (x1 >= 0 && x1 < WW && y0 >= 0 && y0 < HH) ? 1.f : 0.f;
    float v10 = (x0 >= 0 && x0 < WW && y1 >= 0 && y1 < HH) ? 1.f : 0.f;
    float v11 = (x1 >= 0 && x1 < WW && y1 >= 0 && y1 < HH) ? 1.f : 0.f;

    int cx0 = min(max(x0, 0), WW-1), cx1 = min(max(x1, 0), WW-1);
    int cy0 = min(max(y0, 0), HH-1), cy1 = min(max(y1, 0), HH-1);

    float w00 = (1.f-wy)*(1.f-wx) * v00;
    float w01 = (1.f-wy)*wx       * v01;
    float w10 = wy*(1.f-wx)       * v10;
    float w11 = wy*wx             * v11;

    int o00 = cy0*WW + cx0, o01 = cy0*WW + cx1;
    int o10 = cy1*WW + cx0, o11 = cy1*WW + cx1;

    const float* fb = feat + (size_t)b*CC_FEAT*HW;
    float* ob = g_feat2 + (size_t)b*CC_FEAT*HW + y*WW + x;
#pragma unroll 4
    for (int c = 0; c < CC_FEAT; c++) {
        const float* p = fb + c*HW;
        ob[c*HW] = w00*p[o00] + w01*p[o01] + w10*p[o10] + w11*p[o11];
    }
}

// ---------------- 3) correlation (49 disp, mean over 96 ch) + leaky ----------------
// block: (32,8) threads, tile 32x8 pixels; smem holds feat2 chunk (8ch x 14 x 38)
__global__ void __launch_bounds__(256) corr_k(const float* __restrict__ f1)
{
    __shared__ float s2[8][14][38];
    const int tx = threadIdx.x, ty = threadIdx.y;
    const int tid = ty*32 + tx;
    const int x0 = blockIdx.x * 32, y0 = blockIdx.y * 8;
    const int b = blockIdx.z;
    const int x = x0 + tx, y = y0 + ty;

    float acc[ND];
#pragma unroll
    for (int d = 0; d < ND; d++) acc[d] = 0.f;

    for (int cc0 = 0; cc0 < CC_FEAT; cc0 += 8) {
        for (int i = tid; i < 8*14*38; i += 256) {
            int ci  = i / (14*38);
            int rem = i - ci*(14*38);
            int r   = rem / 38;
            int cl  = rem - r*38;
            int gy = y0 + r - MD, gx = x0 + cl - MD;
            float v = 0.f;
            if (gy >= 0 && gy < HH && gx >= 0 && gx < WW)
                v = g_feat2[((b*CC_FEAT + cc0 + ci)*HH + gy)*WW + gx];
            s2[ci][r][cl] = v;
        }
        __syncthreads();

#pragma unroll 1
        for (int ci = 0; ci < 8; ci++) {
            float fv = f1[((b*CC_FEAT + cc0 + ci)*HH + y)*WW + x];
#pragma unroll
            for (int dy = 0; dy < 7; dy++)
#pragma unroll
                for (int dx = 0; dx < 7; dx++)
                    acc[dy*7 + dx] += fv * s2[ci][ty + dy][tx + dx];
        }
        __syncthreads();
    }

#pragma unroll
    for (int d = 0; d < ND; d++) {
        float v = acc[d] * (1.f / 96.f);
        v = (v >= 0.f) ? v : 0.1f * v;
        g_corr[((b*ND + d)*HH + y)*WW + x] = v;
    }
}

// ---------------- 4) direct conv (NCHW), FFMA2 dual-pixel, smem-tiled ----------------
// block (32,8); each thread computes 2 pixel rows (ty, ty+8) x OC_N channels.
template<int CI, int CO, int KS, int CCH, int OC_N, bool LEAKY, bool ADD_FLOW>
__global__ void __launch_bounds__(256) conv2d_k(const float* __restrict__ in,
                                                const float* __restrict__ wgt,
                                                const float* __restrict__ bias,
                                                float* __restrict__ out)
{
    constexpr int PADK = KS / 2;
    constexpr int SH = 16 + KS - 1;
    constexpr int SW = 32 + KS - 1;
    __shared__ float s_in[CCH][SH][SW];
    __shared__ unsigned long long s_w[CCH*KS*KS][OC_N];  // duplicated (w,w) pairs

    const int tx = threadIdx.x, ty = threadIdx.y;
    const int tid = ty*32 + tx;
    const int x0 = blockIdx.x * 32, y0 = blockIdx.y * 16;
    constexpr int PER_B = CO / OC_N;
    const int b   = blockIdx.z / PER_B;
    const int ocb = (blockIdx.z % PER_B) * OC_N;

    unsigned long long acc[OC_N];
#pragma unroll
    for (int i = 0; i < OC_N; i++) acc[i] = 0ull;

#pragma unroll 1
    for (int cc0 = 0; cc0 < CI; cc0 += CCH) {
        // input tile (zero padded at borders)
        for (int i = tid; i < CCH*SH*SW; i += 256) {
            int ci  = i / (SH*SW);
            int rem = i - ci*(SH*SW);
            int r   = rem / SW;
            int cl  = rem - r*SW;
            int gy = y0 + r - PADK, gx = x0 + cl - PADK;
            float v = 0.f;
            if (gy >= 0 && gy < HH && gx >= 0 && gx < WW)
                v = in[((b*CI + cc0 + ci)*HH + gy)*WW + gx];
            s_in[ci][r][cl] = v;
        }
        // weight chunk, layout [ci*K*K + k][oc] as duplicated f32 pairs
        for (int i = tid; i < CCH*KS*KS*OC_N; i += 256) {
            int oc   = i % OC_N;
            int rest = i / OC_N;
            int k    = rest % (KS*KS);
            int ci   = rest / (KS*KS);
            float wv = wgt[((ocb + oc)*CI + cc0 + ci)*KS*KS + k];
            s_w[ci*KS*KS + k][oc] = pk2(wv, wv);
        }
        __syncthreads();

#pragma unroll 1
        for (int ci = 0; ci < CCH; ci++) {
#pragma unroll
            for (int ky = 0; ky < KS; ky++) {
#pragma unroll
                for (int kx = 0; kx < KS; kx++) {
                    float i0 = s_in[ci][ty + ky][tx + kx];
                    float i1 = s_in[ci][ty + 8 + ky][tx + kx];
                    unsigned long long ip = pk2(i0, i1);
                    const unsigned long long* wr = s_w[ci*KS*KS + ky*KS + kx];
#pragma unroll
                    for (int oc = 0; oc < OC_N; oc++)
                        fma2(acc[oc], ip, wr[oc]);
                }
            }
        }
        __syncthreads();
    }

    const int x = x0 + tx;
#pragma unroll
    for (int oc = 0; oc < OC_N; oc++) {
        float r0, r1;
        upk2(acc[oc], r0, r1);
        float bv = bias[ocb + oc];
        r0 += bv; r1 += bv;
        if (LEAKY) {
            r0 = (r0 >= 0.f) ? r0 : 0.1f * r0;
            r1 = (r1 >= 0.f) ? r1 : 0.1f * r1;
        }
        if (ADD_FLOW) {
            r0 += g_flow[((b*2 + ocb + oc)*HH + y0 + ty    )*WW + x];
            r1 += g_flow[((b*2 + ocb + oc)*HH + y0 + ty + 8)*WW + x];
        }
        out[((b*CO + ocb + oc)*HH + y0 + ty    )*WW + x] = r0;
        out[((b*CO + ocb + oc)*HH + y0 + ty + 8)*WW + x] = r1;
    }
}

// ---------------- launch ----------------
extern "C" void kernel_launch(void* const* d_in, const int* in_sizes, int n_in,
                              void* d_out, int out_size)
{
    // metadata order:
    // 0 tensor1 (unused), 1 tensor2 (unused), 2 features_tensor1, 3 features_tensor2,
    // 4 flow_tensor, 5 w_upflow, 6 w1, 7 b1, 8 w2, 9 b2, 10 w3, 11 b3, 12 w4, 13 b4
    const float* f1      = (const float*)d_in[2];
    const float* f2      = (const float*)d_in[3];
    const float* flow_in = (const float*)d_in[4];
    const float* w_up    = (const float*)d_in[5];
    const float* w1 = (const float*)d_in[6];
    const float* b1 = (const float*)d_in[7];
    const float* w2 = (const float*)d_in[8];
    const float* b2 = (const float*)d_in[9];
    const float* w3 = (const float*)d_in[10];
    const float* b3 = (const float*)d_in[11];
    const float* w4 = (const float*)d_in[12];
    const float* b4 = (const float*)d_in[13];
    float* out = (float*)d_out;

    void *pcorr, *px1, *px2, *px3;
    cudaGetSymbolAddress(&pcorr, g_corr);
    cudaGetSymbolAddress(&px1,   g_x1);
    cudaGetSymbolAddress(&px2,   g_x2);
    cudaGetSymbolAddress(&px3,   g_x3);

    // 1) upflow
    upflow_k<<<(BB*2*HW + 255)/256, 256>>>(flow_in, w_up);
    // 2) backwarp
    backwarp_k<<<(BB*HW + 255)/256, 256>>>(f2);
    // 3) correlation + leaky
    corr_k<<<dim3(WW/32, HH/8, BB), dim3(32, 8)>>>(f1);
    // 4) conv chain
    conv2d_k<49, 128, 3, 7, 8, true,  false><<<dim3(WW/32, HH/16, BB*16), dim3(32, 8)>>>(
        (const float*)pcorr, w1, b1, (float*)px1);
    conv2d_k<128, 64, 3, 8, 8, true,  false><<<dim3(WW/32, HH/16, BB*8),  dim3(32, 8)>>>(
        (const float*)px1,   w2, b2, (float*)px2);
    conv2d_k<64,  32, 3, 8, 8, true,  false><<<dim3(WW/32, HH/16, BB*4),  dim3(32, 8)>>>(
        (const float*)px2,   w3, b3, (float*)px3);
    conv2d_k<32,   2, 5, 8, 2, false, true ><<<dim3(WW/32, HH/16, BB*1),  dim3(32, 8)>>>(
        (const float*)px3,   w4, b4, out);
}

// round 4
// speedup vs baseline: 1.2138x; 1.2138x over previous
#include <cuda_runtime.h>
#include <cuda_bf16.h>

// Problem constants
#define BB 4
#define CC_FEAT 96
#define HH 192
#define WW 192
#define HW (HH*WW)
#define MD 3
#define ND 49

// ---------------- scratch (device globals; no allocation allowed) ----------------
__device__ float g_flow [BB*2*HW];          // upsampled flow (B,2,192,192)
__device__ float g_feat2[BB*CC_FEAT*HW];    // warped features2
__device__ float g_corr [BB*ND*HW];         // correlation output (leaky)
__device__ float g_x1   [BB*128*HW];
__device__ float g_x2   [BB*64 *HW];
__device__ float g_x3   [BB*32 *HW];

// ---------------- f32x2 helpers (FFMA2: 2x fp32 throughput, PTX-only) ----------------
__device__ __forceinline__ unsigned long long pk2(float lo, float hi) {
    unsigned long long r;
    asm("mov.b64 %0, {%1, %2};" : "=l"(r) : "f"(lo), "f"(hi));
    return r;
}
__device__ __forceinline__ void upk2(unsigned long long v, float& lo, float& hi) {
    asm("mov.b64 {%0, %1}, %2;" : "=f"(lo), "=f"(hi) : "l"(v));
}
__device__ __forceinline__ void fma2(unsigned long long& d, unsigned long long a, unsigned long long b) {
    asm("fma.rn.f32x2 %0, %1, %2, %0;" : "+l"(d) : "l"(a), "l"(b));
}

// ---------------- 1) upflow: ConvTranspose2d(2,2,k=4,s=2,p=1, groups=2) ----------------
__global__ void __launch_bounds__(256) upflow_k(const float* __restrict__ fl,
                                                const float* __restrict__ w)
{
    int idx = blockIdx.x * 256 + threadIdx.x;
    if (idx >= BB*2*HW) return;
    int x = idx % WW;
    int y = (idx / WW) % HH;
    int g = (idx / HW) % 2;
    int b = idx / (2*HW);
    float acc = 0.f;
#pragma unroll
    for (int ky = 0; ky < 4; ky++) {
        int t = y + ky - 2;
        if (t & 1) continue;
        int iy = t >> 1;
        if (iy < 0 || iy >= 96) continue;
#pragma unroll
        for (int kx = 0; kx < 4; kx++) {
            int s = x + kx - 2;
            if (s & 1) continue;
            int ix = s >> 1;
            if (ix < 0 || ix >= 96) continue;
            // flipped kernel (w[:,:,::-1,::-1])
            acc += w[g*16 + (3-ky)*4 + (3-kx)] * fl[((b*2 + g)*96 + iy)*96 + ix];
        }
    }
    g_flow[idx] = acc;
}

// ---------------- 2) backwarp: bilinear warp of features2 by 2.5*flow ----------------
__global__ void __launch_bounds__(256) backwarp_k(const float* __restrict__ feat)
{
    int idx = blockIdx.x * 256 + threadIdx.x;
    if (idx >= BB*HW) return;
    int x = idx % WW;
    int y = (idx / WW) % HH;
    int b = idx / HW;

    float fx = 2.5f * g_flow[(b*2 + 0)*HW + y*WW + x];
    float fy = 2.5f * g_flow[(b*2 + 1)*HW + y*WW + x];
    float gx = (float)x + fx;
    float gy = (float)y + fy;
    float x0f = floorf(gx), y0f = floorf(gy);
    float wx = gx - x0f, wy = gy - y0f;
    int x0 = (int)x0f, y0 = (int)y0f;
    int x1 = x0 + 1,  y1 = y0 + 1;

    float v00 = (x0 >= 0 && x0 < WW && y0 >= 0 && y0 < HH) ? 1.f : 0.f;
    float v01 = (x1 >= 0 && x1 < WW && y0 >= 0 && y0 < HH) ? 1.f : 0.f;
    float v10 = (x0 >= 0 && x0 < WW && y1 >= 0 && y1 < HH) ? 1.f : 0.f;
    float v11 = (x1 >= 0 && x1 < WW && y1 >= 0 && y1 < HH) ? 1.f : 0.f;

    int cx0 = min(max(x0, 0), WW-1), cx1 = min(max(x1, 0), WW-1);
    int cy0 = min(max(y0, 0), HH-1), cy1 = min(max(y1, 0), HH-1);

    float w00 = (1.f-wy)*(1.f-wx) * v00;
    float w01 = (1.f-wy)*wx       * v01;
    float w10 = wy*(1.f-wx)       * v10;
    float w11 = wy*wx             * v11;

    int o00 = cy0*WW + cx0, o01 = cy0*WW + cx1;
    int o10 = cy1*WW + cx0, o11 = cy1*WW + cx1;

    const float* fb = feat + (size_t)b*CC_FEAT*HW;
    float* ob = g_feat2 + (size_t)b*CC_FEAT*HW + y*WW + x;
#pragma unroll 4
    for (int c = 0; c < CC_FEAT; c++) {
        const float* p = fb + c*HW;
        ob[c*HW] = w00*p[o00] + w01*p[o01] + w10*p[o10] + w11*p[o11];
    }
}

// ---------------- 3) correlation (49 disp, mean over 96 ch) + leaky ----------------
// block: (32,8) threads, tile 32x8 pixels; smem holds feat2 chunk (8ch x 14 x 38)
__global__ void __launch_bounds__(256) corr_k(const float* __restrict__ f1)
{
    __shared__ float s2[8][14][38];
    const int tx = threadIdx.x, ty = threadIdx.y;
    const int tid = ty*32 + tx;
    const int x0 = blockIdx.x * 32, y0 = blockIdx.y * 8;
    const int b = blockIdx.z;
    const int x = x0 + tx, y = y0 + ty;

    float acc[ND];
#pragma unroll
    for (int d = 0; d < ND; d++) acc[d] = 0.f;

    for (int cc0 = 0; cc0 < CC_FEAT; cc0 += 8) {
        for (int i = tid; i < 8*14*38; i += 256) {
            int ci  = i / (14*38);
            int rem = i - ci*(14*38);
            int r   = rem / 38;
            int cl  = rem - r*38;
            int gy = y0 + r - MD, gx = x0 + cl - MD;
            float v = 0.f;
            if (gy >= 0 && gy < HH && gx >= 0 && gx < WW)
                v = g_feat2[((b*CC_FEAT + cc0 + ci)*HH + gy)*WW + gx];
            s2[ci][r][cl] = v;
        }
        __syncthreads();

#pragma unroll 1
        for (int ci = 0; ci < 8; ci++) {
            float fv = f1[((b*CC_FEAT + cc0 + ci)*HH + y)*WW + x];
#pragma unroll
            for (int dy = 0; dy < 7; dy++)
#pragma unroll
                for (int dx = 0; dx < 7; dx++)
                    acc[dy*7 + dx] += fv * s2[ci][ty + dy][tx + dx];
        }
        __syncthreads();
    }

#pragma unroll
    for (int d = 0; d < ND; d++) {
        float v = acc[d] * (1.f / 96.f);
        v = (v >= 0.f) ? v : 0.1f * v;
        g_corr[((b*ND + d)*HH + y)*WW + x] = v;
    }
}

// ---------------- 4) direct conv (NCHW), FFMA2, 4 rows/thread, vector weight LDS ----
// block (32,8); y-tile = 32. Each thread computes rows ty, ty+8, ty+16, ty+24
// for OC_N output channels. Weights read as 16B LDS.128 (2 duplicated f32 pairs).
// Per inner (ci,ky,kx): 4 scalar LDS + OC_N/2 LDS.128 + 2*OC_N FMA2.
template<int CI, int CO, int KS, int CCH, int OC_N, bool LEAKY, bool ADD_FLOW>
__global__ void __launch_bounds__(256) conv2d_k(const float* __restrict__ in,
                                                const float* __restrict__ wgt,
                                                const float* __restrict__ bias,
                                                float* __restrict__ out)
{
    constexpr int PADK = KS / 2;
    constexpr int YT = 32;                 // y-tile
    constexpr int SH = YT + KS - 1;
    constexpr int SW = 32 + KS - 1;
    __shared__ float s_in[CCH][SH][SW];
    __shared__ __align__(16) unsigned long long s_w[CCH*KS*KS][OC_N]; // duplicated (w,w)

    const int tx = threadIdx.x, ty = threadIdx.y;
    const int tid = ty*32 + tx;
    const int x0 = blockIdx.x * 32, y0 = blockIdx.y * YT;
    constexpr int PER_B = CO / OC_N;
    const int b   = blockIdx.z / PER_B;
    const int ocb = (blockIdx.z % PER_B) * OC_N;

    unsigned long long acc0[OC_N];   // rows ty, ty+8
    unsigned long long acc1[OC_N];   // rows ty+16, ty+24
#pragma unroll
    for (int i = 0; i < OC_N; i++) { acc0[i] = 0ull; acc1[i] = 0ull; }

#pragma unroll 1
    for (int cc0 = 0; cc0 < CI; cc0 += CCH) {
        // input tile (zero padded at borders)
        for (int i = tid; i < CCH*SH*SW; i += 256) {
            int ci  = i / (SH*SW);
            int rem = i - ci*(SH*SW);
            int r   = rem / SW;
            int cl  = rem - r*SW;
            int gy = y0 + r - PADK, gx = x0 + cl - PADK;
            float v = 0.f;
            if (gy >= 0 && gy < HH && gx >= 0 && gx < WW)
                v = in[((b*CI + cc0 + ci)*HH + gy)*WW + gx];
            s_in[ci][r][cl] = v;
        }
        // weight chunk, layout [ci*K*K + k][oc] as duplicated f32 pairs
        for (int i = tid; i < CCH*KS*KS*OC_N; i += 256) {
            int oc   = i % OC_N;
            int rest = i / OC_N;
            int k    = rest % (KS*KS);
            int ci   = rest / (KS*KS);
            float wv = wgt[((ocb + oc)*CI + cc0 + ci)*KS*KS + k];
            s_w[ci*KS*KS + k][oc] = pk2(wv, wv);
        }
        __syncthreads();

#pragma unroll 1
        for (int ci = 0; ci < CCH; ci++) {
#pragma unroll
            for (int ky = 0; ky < KS; ky++) {
#pragma unroll
                for (int kx = 0; kx < KS; kx++) {
                    float i0 = s_in[ci][ty      + ky][tx + kx];
                    float i1 = s_in[ci][ty +  8 + ky][tx + kx];
                    float i2 = s_in[ci][ty + 16 + ky][tx + kx];
                    float i3 = s_in[ci][ty + 24 + ky][tx + kx];
                    unsigned long long p01 = pk2(i0, i1);
                    unsigned long long p23 = pk2(i2, i3);
                    const ulonglong2* wr =
                        reinterpret_cast<const ulonglong2*>(s_w[ci*KS*KS + ky*KS + kx]);
#pragma unroll
                    for (int j = 0; j < OC_N/2; j++) {
                        ulonglong2 w2 = wr[j];
                        fma2(acc0[2*j  ], p01, w2.x);
                        fma2(acc0[2*j+1], p01, w2.y);
                        fma2(acc1[2*j  ], p23, w2.x);
                        fma2(acc1[2*j+1], p23, w2.y);
                    }
                }
            }
        }
        __syncthreads();
    }

    const int x = x0 + tx;
#pragma unroll
    for (int oc = 0; oc < OC_N; oc++) {
        float r0, r1, r2, r3;
        upk2(acc0[oc], r0, r1);
        upk2(acc1[oc], r2, r3);
        float bv = bias[ocb + oc];
        r0 += bv; r1 += bv; r2 += bv; r3 += bv;
        if (LEAKY) {
            r0 = (r0 >= 0.f) ? r0 : 0.1f * r0;
            r1 = (r1 >= 0.f) ? r1 : 0.1f * r1;
            r2 = (r2 >= 0.f) ? r2 : 0.1f * r2;
            r3 = (r3 >= 0.f) ? r3 : 0.1f * r3;
        }
        if (ADD_FLOW) {
            r0 += g_flow[((b*2 + ocb + oc)*HH + y0 + ty     )*WW + x];
            r1 += g_flow[((b*2 + ocb + oc)*HH + y0 + ty +  8)*WW + x];
            r2 += g_flow[((b*2 + ocb + oc)*HH + y0 + ty + 16)*WW + x];
            r3 += g_flow[((b*2 + ocb + oc)*HH + y0 + ty + 24)*WW + x];
        }
        out[((b*CO + ocb + oc)*HH + y0 + ty     )*WW + x] = r0;
        out[((b*CO + ocb + oc)*HH + y0 + ty +  8)*WW + x] = r1;
        out[((b*CO + ocb + oc)*HH + y0 + ty + 16)*WW + x] = r2;
        out[((b*CO + ocb + oc)*HH + y0 + ty + 24)*WW + x] = r3;
    }
}

// ---------------- launch ----------------
extern "C" void kernel_launch(void* const* d_in, const int* in_sizes, int n_in,
                              void* d_out, int out_size)
{
    // metadata order:
    // 0 tensor1 (unused), 1 tensor2 (unused), 2 features_tensor1, 3 features_tensor2,
    // 4 flow_tensor, 5 w_upflow, 6 w1, 7 b1, 8 w2, 9 b2, 10 w3, 11 b3, 12 w4, 13 b4
    const float* f1      = (const float*)d_in[2];
    const float* f2      = (const float*)d_in[3];
    const float* flow_in = (const float*)d_in[4];
    const float* w_up    = (const float*)d_in[5];
    const float* w1 = (const float*)d_in[6];
    const float* b1 = (const float*)d_in[7];
    const float* w2 = (const float*)d_in[8];
    const float* b2 = (const float*)d_in[9];
    const float* w3 = (const float*)d_in[10];
    const float* b3 = (const float*)d_in[11];
    const float* w4 = (const float*)d_in[12];
    const float* b4 = (const float*)d_in[13];
    float* out = (float*)d_out;

    void *pcorr, *px1, *px2, *px3;
    cudaGetSymbolAddress(&pcorr, g_corr);
    cudaGetSymbolAddress(&px1,   g_x1);
    cudaGetSymbolAddress(&px2,   g_x2);
    cudaGetSymbolAddress(&px3,   g_x3);

    // 1) upflow
    upflow_k<<<(BB*2*HW + 255)/256, 256>>>(flow_in, w_up);
    // 2) backwarp
    backwarp_k<<<(BB*HW + 255)/256, 256>>>(f2);
    // 3) correlation + leaky
    corr_k<<<dim3(WW/32, HH/8, BB), dim3(32, 8)>>>(f1);
    // 4) conv chain (y-tile 32)
    conv2d_k<49, 128, 3, 7, 8, true,  false><<<dim3(WW/32, HH/32, BB*16), dim3(32, 8)>>>(
        (const float*)pcorr, w1, b1, (float*)px1);
    conv2d_k<128, 64, 3, 8, 8, true,  false><<<dim3(WW/32, HH/32, BB*8),  dim3(32, 8)>>>(
        (const float*)px1,   w2, b2, (float*)px2);
    conv2d_k<64,  32, 3, 8, 8, true,  false><<<dim3(WW/32, HH/32, BB*4),  dim3(32, 8)>>>(
        (const float*)px2,   w3, b3, (float*)px3);
    conv2d_k<32,   2, 5, 8, 2, false, true ><<<dim3(WW/32, HH/32, BB*1),  dim3(32, 8)>>>(
        (const float*)px3,   w4, b4, out);
}